// round 4
// baseline (speedup 1.0000x reference)
#include <cuda_runtime.h>
#include <cuda_bf16.h>

// BCELoss(reduce=False) with "correct-side" masking.
//   y in {0,1}. q = y ? p : 1-p.  loss = (q > 0.5) ? 0 : -max(log q, -100)
// log(1-p) only evaluated when p >= 0.5 -> 1-p exact (Sterbenz), matches
// reference log1p(-p) to fp32 precision.
//
// Round 3: 8 floats/thread (2x float4 per input, front-batched loads for
// MLP=4), streaming cache hints (__ldcs/__stcs) since every byte is touched
// exactly once — avoid L2 allocate pressure on the write path.

__device__ __forceinline__ float bce_elem(float p, float y) {
    float q = (y > 0.5f) ? p : (1.0f - p);
    if (q > 0.5f) return 0.0f;
    return -fmaxf(__logf(q), -100.0f);
}

__device__ __forceinline__ float4 bce_vec4(float4 p, float4 y) {
    float4 o;
    o.x = bce_elem(p.x, y.x);
    o.y = bce_elem(p.y, y.y);
    o.z = bce_elem(p.z, y.z);
    o.w = bce_elem(p.w, y.w);
    return o;
}

__global__ void __launch_bounds__(256)
neo_loss_vec8(const float4* __restrict__ pred,
              const float4* __restrict__ actual,
              float4* __restrict__ out,
              int n4) {
    // each thread handles 2 float4 slots: base and base+256 (coalesced)
    int base = blockIdx.x * 512 + threadIdx.x;
    int i1 = base + 256;

    if (i1 < n4) {
        // front-batch all 4 loads -> MLP=4 outstanding LDG.128 per thread
        float4 p0 = __ldcs(&pred[base]);
        float4 p1 = __ldcs(&pred[i1]);
        float4 y0 = __ldcs(&actual[base]);
        float4 y1 = __ldcs(&actual[i1]);
        float4 o0 = bce_vec4(p0, y0);
        float4 o1 = bce_vec4(p1, y1);
        __stcs(&out[base], o0);
        __stcs(&out[i1], o1);
    } else if (base < n4) {
        float4 p0 = __ldcs(&pred[base]);
        float4 y0 = __ldcs(&actual[base]);
        __stcs(&out[base], bce_vec4(p0, y0));
    }
}

__global__ void neo_loss_tail(const float* __restrict__ pred,
                              const float* __restrict__ actual,
                              float* __restrict__ out,
                              int start, int n) {
    int i = start + blockIdx.x * blockDim.x + threadIdx.x;
    if (i >= n) return;
    out[i] = bce_elem(pred[i], actual[i]);
}

extern "C" void kernel_launch(void* const* d_in, const int* in_sizes, int n_in,
                              void* d_out, int out_size) {
    const float* pred   = (const float*)d_in[0];
    const float* actual = (const float*)d_in[1];
    float* out = (float*)d_out;
    int n = in_sizes[0];

    int n4 = n >> 2;            // float4 count
    int vec_elems = n4 << 2;

    if (n4 > 0) {
        // 512 float4 slots per block (2 per thread, 256 threads)
        int blocks = (n4 + 511) / 512;
        neo_loss_vec8<<<blocks, 256>>>(
            (const float4*)pred, (const float4*)actual, (float4*)out, n4);
    }
    if (vec_elems < n) {
        int rem = n - vec_elems;
        neo_loss_tail<<<(rem + 255) / 256, 256>>>(pred, actual, out, vec_elems, n);
    }
}

// round 5
// speedup vs baseline: 1.0312x; 1.0312x over previous
#include <cuda_runtime.h>
#include <cuda_bf16.h>

// BCELoss(reduce=False) with "correct-side" masking.
//   y in {0,1}. q = y ? p : 1-p.  loss = (q > 0.5) ? 0 : -max(log q, -100)
// log(1-p) only evaluated when p >= 0.5 -> 1-p exact (Sterbenz), matches
// reference log1p(-p) to fp32 precision.
//
// Round 4: revert cache-op hints (R3 showed DRAM% drop with __ldcs/__stcs;
// default .wb/.ca was faster in R2). Keep 8 floats/thread with 4
// front-batched LDG.128 for low per-byte instruction cost. 512-thread
// blocks: longer sequential sector streams per SM, less CTA churn.

__device__ __forceinline__ float bce_elem(float p, float y) {
    float q = (y > 0.5f) ? p : (1.0f - p);
    if (q > 0.5f) return 0.0f;
    return -fmaxf(__logf(q), -100.0f);
}

__device__ __forceinline__ float4 bce_vec4(float4 p, float4 y) {
    float4 o;
    o.x = bce_elem(p.x, y.x);
    o.y = bce_elem(p.y, y.y);
    o.z = bce_elem(p.z, y.z);
    o.w = bce_elem(p.w, y.w);
    return o;
}

__global__ void __launch_bounds__(512)
neo_loss_vec8(const float4* __restrict__ pred,
              const float4* __restrict__ actual,
              float4* __restrict__ out,
              int n4) {
    // each thread handles 2 float4 slots: base and base+512 (coalesced)
    int base = blockIdx.x * 1024 + threadIdx.x;
    int i1 = base + 512;

    if (i1 < n4) {
        // front-batch all 4 loads -> 4 outstanding LDG.128 per thread
        float4 p0 = pred[base];
        float4 p1 = pred[i1];
        float4 y0 = actual[base];
        float4 y1 = actual[i1];
        out[base] = bce_vec4(p0, y0);
        out[i1]   = bce_vec4(p1, y1);
    } else if (base < n4) {
        float4 p0 = pred[base];
        float4 y0 = actual[base];
        out[base] = bce_vec4(p0, y0);
    }
}

__global__ void neo_loss_tail(const float* __restrict__ pred,
                              const float* __restrict__ actual,
                              float* __restrict__ out,
                              int start, int n) {
    int i = start + blockIdx.x * blockDim.x + threadIdx.x;
    if (i >= n) return;
    out[i] = bce_elem(pred[i], actual[i]);
}

extern "C" void kernel_launch(void* const* d_in, const int* in_sizes, int n_in,
                              void* d_out, int out_size) {
    const float* pred   = (const float*)d_in[0];
    const float* actual = (const float*)d_in[1];
    float* out = (float*)d_out;
    int n = in_sizes[0];

    int n4 = n >> 2;            // float4 count
    int vec_elems = n4 << 2;

    if (n4 > 0) {
        // 1024 float4 slots per block (2 per thread, 512 threads)
        int blocks = (n4 + 1023) / 1024;
        neo_loss_vec8<<<blocks, 512>>>(
            (const float4*)pred, (const float4*)actual, (float4*)out, n4);
    }
    if (vec_elems < n) {
        int rem = n - vec_elems;
        neo_loss_tail<<<(rem + 255) / 256, 256>>>(pred, actual, out, vec_elems, n);
    }
}